// round 1
// baseline (speedup 1.0000x reference)
#include <cuda_runtime.h>
#include <math.h>

#define NT   4096      // trees
#define KC   16        // children
#define DM   256       // DOUT
#define GD   1024      // 4*DOUT
#define NCMB 5         // recurrent combos: (j0,f),(j0,b),(j1,f),(j2,f),(j3,f)

// ---------------- scratch (device globals; no allocations allowed) ----------
__device__ float s_xseq [(long)NT*KC*DM];        // gathered child h
__device__ float s_cseq [(long)NT*KC*DM];        // gathered child c
__device__ int   s_len  [NT];
__device__ float s_Wih5 [(long)NCMB*GD*DM];      // packed input weights (5 combos)
__device__ float s_Whh5 [(long)NCMB*GD*DM];      // packed recurrent weights
__device__ float s_b5   [NCMB*GD];               // bih+bhh per combo
__device__ float s_WihB [3L*GD*DM];              // backward input weights j=1..3
__device__ float s_hb   [3*GD];                  // h0@Whh^T + biases (bwd one-step)
__device__ float s_Gx   [(long)NCMB*NT*KC*GD];   // hoisted x-part gates (proc order)
__device__ float s_h    [(long)NCMB*NT*DM];      // recurrent h state
__device__ float s_c    [(long)NCMB*NT*DM];      // recurrent c state
__device__ float s_g    [(long)NCMB*NT*GD];      // per-step gate pre-activations
__device__ float s_Wx   [(long)NT*GD];           // x @ W_w^T + W_b
__device__ float s_ycat0[(long)NT*KC*2*DM];      // j0 [yf|yb] concat
__device__ float s_ylcat[3L*NT*2*DM];            // j1..3 [yf(last)|yb(last)]
__device__ float s_xlast[(long)NT*DM];           // xseq at k=len-1
__device__ float s_gB   [3L*NT*GD];              // bwd one-step gates j=1..3
__device__ float s_ys0  [(long)NT*KC*DM];        // fc-projected j0 outputs
__device__ float s_ysl  [3L*NT*DM];              // fc-projected j1..3 at last

__device__ __forceinline__ float sigf(float x){ return 1.f/(1.f+expf(-x)); }

// ---------------- prep: pack weights for uniform batched strides ------------
__global__ void prep_weights(const float* __restrict__ Wih, const float* __restrict__ Whh,
                             const float* __restrict__ bih, const float* __restrict__ bhh){
    const int map5[5]={0,1,2,4,6};   // (j,dir) flat = j*2+dir
    const int mapB[3]={3,5,7};       // (j,1) for j=1..3
    long idx = (long)blockIdx.x*blockDim.x + threadIdx.x;
    long stride = (long)gridDim.x*blockDim.x;
    for (long i=idx; i<(long)NCMB*GD*DM; i+=stride){
        int cmb = (int)(i/((long)GD*DM)); long r = i%((long)GD*DM);
        s_Wih5[i]=Wih[(long)map5[cmb]*GD*DM + r];
        s_Whh5[i]=Whh[(long)map5[cmb]*GD*DM + r];
    }
    for (long i=idx; i<3L*GD*DM; i+=stride){
        int jb = (int)(i/((long)GD*DM)); long r = i%((long)GD*DM);
        s_WihB[i]=Wih[(long)mapB[jb]*GD*DM + r];
    }
    for (long i=idx; i<(long)NCMB*GD; i+=stride){
        int cmb=(int)(i/GD); int o=(int)(i%GD);
        s_b5[i]=bih[map5[cmb]*GD+o]+bhh[map5[cmb]*GD+o];
    }
}

// ---------------- gather child states ---------------------------------------
__global__ void gather_k(const float* __restrict__ h_tensor,
                         const float* __restrict__ c_tensor,
                         const int*   __restrict__ indice){
    long i = (long)blockIdx.x*blockDim.x + threadIdx.x;   // float4 index
    if (i >= (long)NT*KC*(DM/4)) return;
    long nk = i / (DM/4);
    int  d4 = (int)(i % (DM/4));
    int id = indice[nk]; if (id < 0) id = 0;
    ((float4*)s_xseq)[i] = ((const float4*)h_tensor)[(long)id*(DM/4)+d4];
    ((float4*)s_cseq)[i] = ((const float4*)c_tensor)[(long)id*(DM/4)+d4];
}

// ---------------- lengths + initial states ----------------------------------
__global__ void meta_k(const int* __restrict__ indice,
                       const float* __restrict__ h0, const float* __restrict__ c0){
    long idx = (long)blockIdx.x*blockDim.x + threadIdx.x;
    long stride = (long)gridDim.x*blockDim.x;
    for (long n=idx; n<NT; n+=stride){
        int l=0;
        #pragma unroll
        for (int k=0;k<KC;k++) if (indice[n*KC+k] != -1) l++;
        s_len[n]=l;
    }
    const int jmap[5]={0,0,1,2,3};
    for (long i=idx; i<(long)NCMB*NT*DM; i+=stride){
        int cmb = (int)(i/((long)NT*DM)); int d = (int)(i%DM);
        s_h[i] = h0[jmap[cmb]*DM+d];
        s_c[i] = c0[jmap[cmb]*DM+d];
    }
}

// ---------------- xlast gather (needs lengths) -------------------------------
__global__ void xlast_k(){
    long i = (long)blockIdx.x*blockDim.x + threadIdx.x;   // float4 index
    if (i >= (long)NT*(DM/4)) return;
    int n = (int)(i/(DM/4)); int d4 = (int)(i%(DM/4));
    int last = s_len[n]-1;
    ((float4*)s_xlast)[i] = ((const float4*)s_xseq)[((long)n*KC+last)*(DM/4)+d4];
}

// ---------------- hb = h0 @ Whh_bwd^T + biases (j=1..3) -----------------------
__global__ void hb_k(const float* __restrict__ h0, const float* __restrict__ Whh,
                     const float* __restrict__ bih, const float* __restrict__ bhh){
    int idx = blockIdx.x*blockDim.x + threadIdx.x;
    if (idx >= 3*GD) return;
    int jb = idx/GD, o = idx%GD;
    int jd2 = 2*(jb+1)+1;   // 3,5,7
    const float* w = Whh + (long)jd2*GD*DM + (long)o*DM;
    const float* h = h0 + (jb+1)*DM;
    float acc=0.f;
    #pragma unroll 8
    for (int d=0; d<DM; d++) acc += h[d]*w[d];
    s_hb[idx] = acc + bih[jd2*GD+o] + bhh[jd2*GD+o];
}

// ---------------- generic batched SGEMM: C = A @ B^T (+bias)(+Cadd) ----------
// A:[M,K] rm, B:[N,K] rm. Tiles 128x128x16, 8x8 microtile, 256 thr.
// All M%128==0, N%128==0, K%16==0 here -> no bounds checks.
// rows of A are read at (row ^ xorVal) when z == xorZ (time-reverse fold).
__global__ void __launch_bounds__(256) gemm_k(
    const float* __restrict__ A, long aBatch,
    const float* __restrict__ B, long bBatch,
    const float* __restrict__ bias, long biasBatch,
    const float* __restrict__ Cadd, long caddBatch, int caddRow,
    float* __restrict__ C, long cBatch, int cRow,
    int M, int N, int K, int xorZ, int xorVal)
{
    int z = blockIdx.z;
    const float* Ab = A + (long)z*aBatch;
    const float* Bb = B + (long)z*bBatch;
    const float* biasb = bias ? bias + (long)z*biasBatch : (const float*)0;
    const float* caddb = Cadd ? Cadd + (long)z*caddBatch : (const float*)0;
    float* Cb = C + (long)z*cBatch;
    int rxor = (z==xorZ) ? xorVal : 0;

    int brow = blockIdx.y * 128;
    int bcol = blockIdx.x * 128;
    int tid = threadIdx.x;
    int ty = tid >> 4, tx = tid & 15;

    __shared__ float As[16][128+4];
    __shared__ float Bs[16][128+4];

    float acc[8][8];
    #pragma unroll
    for (int i=0;i<8;i++)
        #pragma unroll
        for (int j=0;j<8;j++) acc[i][j]=0.f;

    int l_row = tid >> 2;          // 0..63
    int l_k   = (tid & 3) * 4;     // 0,4,8,12

    for (int kb = 0; kb < K; kb += 16) {
        #pragma unroll
        for (int l=0;l<2;l++){
            int ar = l_row + l*64;
            int gr = (brow + ar) ^ rxor;
            float4 v = *reinterpret_cast<const float4*>(&Ab[(long)gr*K + kb + l_k]);
            As[l_k+0][ar]=v.x; As[l_k+1][ar]=v.y; As[l_k+2][ar]=v.z; As[l_k+3][ar]=v.w;
        }
        #pragma unroll
        for (int l=0;l<2;l++){
            int br = l_row + l*64;
            float4 v = *reinterpret_cast<const float4*>(&Bb[(long)(bcol+br)*K + kb + l_k]);
            Bs[l_k+0][br]=v.x; Bs[l_k+1][br]=v.y; Bs[l_k+2][br]=v.z; Bs[l_k+3][br]=v.w;
        }
        __syncthreads();
        #pragma unroll
        for (int kk=0; kk<16; kk++){
            float ar[8], br[8];
            #pragma unroll
            for (int i=0;i<8;i++) ar[i] = As[kk][ty*8+i];
            #pragma unroll
            for (int j=0;j<8;j++) br[j] = Bs[kk][tx*8+j];
            #pragma unroll
            for (int i=0;i<8;i++)
                #pragma unroll
                for (int j=0;j<8;j++)
                    acc[i][j] += ar[i]*br[j];
        }
        __syncthreads();
    }

    #pragma unroll
    for (int i=0;i<8;i++){
        int row = brow + ty*8 + i;
        #pragma unroll
        for (int j=0;j<8;j+=4){
            int col = bcol + tx*8 + j;
            float4 v = make_float4(acc[i][j],acc[i][j+1],acc[i][j+2],acc[i][j+3]);
            if (biasb){
                v.x+=biasb[col]; v.y+=biasb[col+1]; v.z+=biasb[col+2]; v.w+=biasb[col+3];
            }
            if (caddb){
                float4 a = *reinterpret_cast<const float4*>(&caddb[(long)row*caddRow + col]);
                v.x+=a.x; v.y+=a.y; v.z+=a.z; v.w+=a.w;
            }
            *reinterpret_cast<float4*>(&Cb[(long)row*cRow + col]) = v;
        }
    }
}

// ---------------- gates + state update per recurrence step -------------------
__global__ void gates_step(int s){
    long i = (long)blockIdx.x*blockDim.x + threadIdx.x;
    if (i >= (long)NCMB*NT*DM) return;
    int cmb = (int)(i/((long)NT*DM));
    long nd = i%((long)NT*DM);
    int n = (int)(nd/DM), d = (int)(nd%DM);
    const float* g = s_g + (long)cmb*NT*GD + (long)n*GD;
    float ig = sigf(g[d]);
    float fg = sigf(g[DM+d]);
    float ug = tanhf(g[2*DM+d]);
    float og = sigf(g[3*DM+d]);
    float cp = s_c[i];
    float cn = fg*cp + ig*ug;
    float hn = og*tanhf(cn);
    if (cmb == 1){                               // j0 backward: prefix-masked
        int kk = 15 - s;
        bool m = kk < s_len[n];
        if (m){ s_c[i]=cn; s_h[i]=hn; }
        s_ycat0[((long)n*KC+kk)*(2*DM) + DM + d] = m ? hn : 0.f;
    } else {                                     // forward: mask-free
        s_c[i]=cn; s_h[i]=hn;
        if (cmb==0) s_ycat0[((long)n*KC+s)*(2*DM) + d] = hn;
        else if (s == s_len[n]-1)
            s_ylcat[((long)(cmb-2)*NT+n)*(2*DM) + d] = hn;
    }
}

// ---------------- one-step backward gates (j=1..3) ---------------------------
__global__ void gates_last(const float* __restrict__ c0){
    long i = (long)blockIdx.x*blockDim.x + threadIdx.x;
    if (i >= 3L*NT*DM) return;
    int jb = (int)(i/((long)NT*DM));
    long nd = i%((long)NT*DM);
    int n = (int)(nd/DM), d = (int)(nd%DM);
    const float* g = s_gB + (long)jb*NT*GD + (long)n*GD;
    float ig=sigf(g[d]), fg=sigf(g[DM+d]), ug=tanhf(g[2*DM+d]), og=sigf(g[3*DM+d]);
    float cp = c0[(jb+1)*DM+d];
    float cn = fg*cp + ig*ug;
    float hn = og*tanhf(cn);
    s_ylcat[((long)jb*NT+n)*(2*DM) + DM + d] = hn;
}

// ---------------- final branch combine ---------------------------------------
__global__ void final_k(float* __restrict__ out){
    int n = blockIdx.x, d = threadIdx.x;
    float wf = s_Wx[(long)n*GD + d];
    float wi = s_Wx[(long)n*GD + DM + d];
    float wu = s_Wx[(long)n*GD + 2*DM + d];
    float wo = s_Wx[(long)n*GD + 3*DM + d];
    int len = s_len[n];
    float bf = 0.f;
    for (int k=0;k<len;k++){
        float y  = s_ys0 [((long)n*KC+k)*DM + d];
        float cc = s_cseq[((long)n*KC+k)*DM + d];
        bf += sigf(wf + y) * cc;
    }
    float bi = sigf (s_ysl[0L*NT*DM + (long)n*DM + d] + wi);
    float bu = tanhf(s_ysl[1L*NT*DM + (long)n*DM + d] + wu);
    float bo = sigf (s_ysl[2L*NT*DM + (long)n*DM + d] + wo);
    float ncv = bi*bu + bf;
    float nhv = bo*tanhf(ncv);
    out[(long)n*DM + d] = nhv;                   // new_h
    out[(long)NT*DM + (long)n*DM + d] = ncv;     // new_c
}

// =============================================================================
extern "C" void kernel_launch(void* const* d_in, const int* in_sizes, int n_in,
                              void* d_out, int out_size) {
    const float* x        = (const float*)d_in[0];
    const float* h_tensor = (const float*)d_in[1];
    const float* c_tensor = (const float*)d_in[2];
    const int*   indice   = (const int*)  d_in[3];
    const float* W_w      = (const float*)d_in[4];
    const float* W_b      = (const float*)d_in[5];
    const float* h0       = (const float*)d_in[6];
    const float* c0       = (const float*)d_in[7];
    const float* Wih      = (const float*)d_in[8];
    const float* Whh      = (const float*)d_in[9];
    const float* bih      = (const float*)d_in[10];
    const float* bhh      = (const float*)d_in[11];
    const float* fc       = (const float*)d_in[12];
    float* out = (float*)d_out;

    float *p_xseq,*p_Wih5,*p_Whh5,*p_b5,*p_Gx,*p_h,*p_Whh5b,*p_g,*p_Wx,
          *p_xlast,*p_WihB,*p_hb,*p_gB,*p_ycat0,*p_ys0,*p_ylcat,*p_ysl;
    cudaGetSymbolAddress((void**)&p_xseq,  s_xseq);
    cudaGetSymbolAddress((void**)&p_Wih5,  s_Wih5);
    cudaGetSymbolAddress((void**)&p_Whh5,  s_Whh5);
    cudaGetSymbolAddress((void**)&p_b5,    s_b5);
    cudaGetSymbolAddress((void**)&p_Gx,    s_Gx);
    cudaGetSymbolAddress((void**)&p_h,     s_h);
    cudaGetSymbolAddress((void**)&p_g,     s_g);
    cudaGetSymbolAddress((void**)&p_Wx,    s_Wx);
    cudaGetSymbolAddress((void**)&p_xlast, s_xlast);
    cudaGetSymbolAddress((void**)&p_WihB,  s_WihB);
    cudaGetSymbolAddress((void**)&p_hb,    s_hb);
    cudaGetSymbolAddress((void**)&p_gB,    s_gB);
    cudaGetSymbolAddress((void**)&p_ycat0, s_ycat0);
    cudaGetSymbolAddress((void**)&p_ys0,   s_ys0);
    cudaGetSymbolAddress((void**)&p_ylcat, s_ylcat);
    cudaGetSymbolAddress((void**)&p_ysl,   s_ysl);
    (void)p_Whh5b; (void)in_sizes; (void)n_in; (void)out_size;

    // 1) pack weights / gather / meta
    prep_weights<<<1024,256>>>(Wih,Whh,bih,bhh);
    gather_k<<<(int)(((long)NT*KC*(DM/4))/256),256>>>(h_tensor,c_tensor,indice);
    meta_k<<<512,256>>>(indice,h0,c0);

    // 2) Wx = x @ W_w^T + W_b        [4096,1024]
    gemm_k<<<dim3(GD/128, NT/128, 1),256>>>(
        x,0, W_w,0, W_b,0, (const float*)0,0,0,
        p_Wx,0,GD, NT,GD,DM, -1,0);

    // 3) Gx = xseq @ Wih5^T + b5, time-reversed rows for combo 1 (z==1)
    gemm_k<<<dim3(GD/128, (NT*KC)/128, NCMB),256>>>(
        p_xseq,0, p_Wih5,(long)GD*DM, p_b5,(long)GD, (const float*)0,0,0,
        p_Gx,(long)NT*KC*GD,GD, NT*KC,GD,DM, 1,15);

    // 4) one-step backward prep
    hb_k<<<12,256>>>(h0,Whh,bih,bhh);
    xlast_k<<<(int)(((long)NT*(DM/4)+255)/256),256>>>();

    // 5) the 16 recurrence steps (5 combos batched per step)
    long gatesN = (long)NCMB*NT*DM;
    for (int s = 0; s < KC; s++){
        gemm_k<<<dim3(GD/128, NT/128, NCMB),256>>>(
            p_h,(long)NT*DM, p_Whh5,(long)GD*DM, (const float*)0,0,
            p_Gx + (long)s*GD, (long)NT*KC*GD, KC*GD,
            p_g,(long)NT*GD,GD, NT,GD,DM, -1,0);
        gates_step<<<(int)((gatesN+255)/256),256>>>(s);
    }

    // 6) backward one-step for j=1..3: gB = xlast @ WihB^T + hb, then gates
    gemm_k<<<dim3(GD/128, NT/128, 3),256>>>(
        p_xlast,0, p_WihB,(long)GD*DM, p_hb,(long)GD, (const float*)0,0,0,
        p_gB,(long)NT*GD,GD, NT,GD,DM, -1,0);
    gates_last<<<(int)((3L*NT*DM+255)/256),256>>>(c0);

    // 7) fc projections
    gemm_k<<<dim3(DM/128, (NT*KC)/128, 1),256>>>(          // j0, all k
        p_ycat0,0, fc,0, (const float*)0,0, (const float*)0,0,0,
        p_ys0,0,DM, NT*KC,DM,2*DM, -1,0);
    gemm_k<<<dim3(DM/128, NT/128, 3),256>>>(               // j1..3 at k=last
        p_ylcat,(long)NT*2*DM, fc + (long)DM*2*DM,(long)DM*2*DM,
        (const float*)0,0, (const float*)0,0,0,
        p_ysl,(long)NT*DM,DM, NT,DM,2*DM, -1,0);

    // 8) final combine -> (new_h, new_c)
    final_k<<<NT,DM>>>(out);
}

// round 3
// speedup vs baseline: 2.0720x; 2.0720x over previous
#include <cuda_runtime.h>
#include <math.h>
#include <stdint.h>

#define NT   4096      // trees
#define KC   16        // children
#define DM   256       // DOUT
#define GD   1024      // 4*DOUT
#define NCMB 5         // recurrent combos: (j0,f),(j0,b),(j1,f),(j2,f),(j3,f)

// ---------------- scratch (device globals; no allocations allowed) ----------
__device__ float s_xseq [(long)NT*KC*DM];
__device__ float s_cseq [(long)NT*KC*DM];
__device__ int   s_len  [NT];
__device__ float s_Wih5 [(long)NCMB*GD*DM];
__device__ float s_Whh5 [(long)NCMB*GD*DM];
__device__ float s_b5   [NCMB*GD];
__device__ float s_WihB [3L*GD*DM];
__device__ float s_hb   [3*GD];
__device__ float s_Gx   [(long)NCMB*NT*KC*GD];
__device__ float s_h    [(long)NCMB*NT*DM];
__device__ float s_c    [(long)NCMB*NT*DM];
__device__ float s_g    [(long)NCMB*NT*GD];
__device__ float s_Wx   [(long)NT*GD];
__device__ float s_ycat0[(long)NT*KC*2*DM];
__device__ float s_ylcat[3L*NT*2*DM];
__device__ float s_xlast[(long)NT*DM];
__device__ float s_gB   [3L*NT*GD];
__device__ float s_ys0  [(long)NT*KC*DM];
__device__ float s_ysl  [3L*NT*DM];

__device__ __forceinline__ float sigf(float x){ return 1.f/(1.f+expf(-x)); }

__device__ __forceinline__ uint32_t f2tf32(float f){
    uint32_t r; asm("cvt.rna.tf32.f32 %0, %1;" : "=r"(r) : "f"(f)); return r;
}

__device__ __forceinline__ void mma_tf32(float4& c,
        uint32_t a0, uint32_t a1, uint32_t a2, uint32_t a3,
        uint32_t b0, uint32_t b1){
    asm volatile(
        "mma.sync.aligned.m16n8k8.row.col.f32.tf32.tf32.f32 "
        "{%0,%1,%2,%3}, {%4,%5,%6,%7}, {%8,%9}, {%0,%1,%2,%3};"
        : "+f"(c.x), "+f"(c.y), "+f"(c.z), "+f"(c.w)
        : "r"(a0), "r"(a1), "r"(a2), "r"(a3), "r"(b0), "r"(b1));
}

// ---------------- prep: pack weights ----------------------------------------
__global__ void prep_weights(const float* __restrict__ Wih, const float* __restrict__ Whh,
                             const float* __restrict__ bih, const float* __restrict__ bhh){
    const int map5[5]={0,1,2,4,6};
    const int mapB[3]={3,5,7};
    long idx = (long)blockIdx.x*blockDim.x + threadIdx.x;
    long stride = (long)gridDim.x*blockDim.x;
    for (long i=idx; i<(long)NCMB*GD*DM; i+=stride){
        int cmb = (int)(i/((long)GD*DM)); long r = i%((long)GD*DM);
        s_Wih5[i]=Wih[(long)map5[cmb]*GD*DM + r];
        s_Whh5[i]=Whh[(long)map5[cmb]*GD*DM + r];
    }
    for (long i=idx; i<3L*GD*DM; i+=stride){
        int jb = (int)(i/((long)GD*DM)); long r = i%((long)GD*DM);
        s_WihB[i]=Wih[(long)mapB[jb]*GD*DM + r];
    }
    for (long i=idx; i<(long)NCMB*GD; i+=stride){
        int cmb=(int)(i/GD); int o=(int)(i%GD);
        s_b5[i]=bih[map5[cmb]*GD+o]+bhh[map5[cmb]*GD+o];
    }
}

// ---------------- gather child states ---------------------------------------
__global__ void gather_k(const float* __restrict__ h_tensor,
                         const float* __restrict__ c_tensor,
                         const int*   __restrict__ indice){
    long i = (long)blockIdx.x*blockDim.x + threadIdx.x;
    if (i >= (long)NT*KC*(DM/4)) return;
    long nk = i / (DM/4);
    int  d4 = (int)(i % (DM/4));
    int id = indice[nk]; if (id < 0) id = 0;
    ((float4*)s_xseq)[i] = ((const float4*)h_tensor)[(long)id*(DM/4)+d4];
    ((float4*)s_cseq)[i] = ((const float4*)c_tensor)[(long)id*(DM/4)+d4];
}

// ---------------- lengths + initial states ----------------------------------
__global__ void meta_k(const int* __restrict__ indice,
                       const float* __restrict__ h0, const float* __restrict__ c0){
    long idx = (long)blockIdx.x*blockDim.x + threadIdx.x;
    long stride = (long)gridDim.x*blockDim.x;
    for (long n=idx; n<NT; n+=stride){
        int l=0;
        #pragma unroll
        for (int k=0;k<KC;k++) if (indice[n*KC+k] != -1) l++;
        s_len[n]=l;
    }
    const int jmap[5]={0,0,1,2,3};
    for (long i=idx; i<(long)NCMB*NT*DM; i+=stride){
        int cmb = (int)(i/((long)NT*DM)); int d = (int)(i%DM);
        s_h[i] = h0[jmap[cmb]*DM+d];
        s_c[i] = c0[jmap[cmb]*DM+d];
    }
}

__global__ void xlast_k(){
    long i = (long)blockIdx.x*blockDim.x + threadIdx.x;
    if (i >= (long)NT*(DM/4)) return;
    int n = (int)(i/(DM/4)); int d4 = (int)(i%(DM/4));
    int last = s_len[n]-1;
    ((float4*)s_xlast)[i] = ((const float4*)s_xseq)[((long)n*KC+last)*(DM/4)+d4];
}

__global__ void hb_k(const float* __restrict__ h0, const float* __restrict__ Whh,
                     const float* __restrict__ bih, const float* __restrict__ bhh){
    int idx = blockIdx.x*blockDim.x + threadIdx.x;
    if (idx >= 3*GD) return;
    int jb = idx/GD, o = idx%GD;
    int jd2 = 2*(jb+1)+1;
    const float* w = Whh + (long)jd2*GD*DM + (long)o*DM;
    const float* h = h0 + (jb+1)*DM;
    float acc=0.f;
    #pragma unroll 8
    for (int d=0; d<DM; d++) acc += h[d]*w[d];
    s_hb[idx] = acc + bih[jd2*GD+o] + bhh[jd2*GD+o];
}

// ---------------- tf32 mma.sync batched GEMM: C = A @ B^T (+bias)(+Cadd) ----
// A:[M,K] rm, B:[N,K] rm, M%128==0, N%128==0, K%32==0.
// 256 thr = 8 warps in 2x4; warp tile 64x32 via m16n8k8 (4 mtiles x 4 ntiles).
// K chunks of 32; fp32->tf32 on smem store; double buffer + reg prefetch.
#define STR 36      // smem row stride in u32 (conflict-free frags, 16B-aligned)
#define ABUF(b) ((b)*128*STR)
#define BBUF(b) (2*128*STR + (b)*128*STR)

__global__ void __launch_bounds__(256) gemm_mma(
    const float* __restrict__ A, long aBatch,
    const float* __restrict__ B, long bBatch,
    const float* __restrict__ bias, long biasBatch,
    const float* __restrict__ Cadd, long caddBatch, int caddRow,
    float* __restrict__ C, long cBatch, int cRow,
    int M, int N, int K, int xorZ, int xorVal)
{
    extern __shared__ uint32_t sm[];
    int tid = threadIdx.x;
    int wid = tid >> 5;
    int lane = tid & 31;
    int g = lane >> 2;          // group id 0..7
    int t = lane & 3;           // thread-in-group 0..3
    int wr = wid >> 2;          // warp row 0..1 (64 rows)
    int wc = wid & 3;           // warp col 0..3 (32 cols)

    int z = blockIdx.z;
    const float* Ab = A + (long)z*aBatch;
    const float* Bb = B + (long)z*bBatch;
    int rxor = (z==xorZ) ? xorVal : 0;
    long brow = (long)blockIdx.y * 128;
    long bcol = (long)blockIdx.x * 128;

    int ldr = tid >> 3;         // 0..31 : row group (x4 per 128 rows)
    int ldc = tid & 7;          // float4 column within 32-float chunk

    float4 pa[4], pb[4];
    #define GLOAD(ch) do {                                                        \
        long kb = (long)(ch)*32;                                                  \
        _Pragma("unroll")                                                         \
        for (int l=0;l<4;l++){                                                    \
            long gr = (brow + ldr + l*32) ^ rxor;                                 \
            pa[l] = *reinterpret_cast<const float4*>(&Ab[gr*K + kb + ldc*4]);     \
            pb[l] = *reinterpret_cast<const float4*>(&Bb[(bcol + ldr + l*32)*K + kb + ldc*4]); \
        }                                                                         \
    } while(0)

    #define SSTORE(buf) do {                                                      \
        _Pragma("unroll")                                                         \
        for (int l=0;l<4;l++){                                                    \
            int r = ldr + l*32;                                                   \
            uint32_t* da = &sm[ABUF(buf) + r*STR + ldc*4];                        \
            da[0]=f2tf32(pa[l].x); da[1]=f2tf32(pa[l].y);                         \
            da[2]=f2tf32(pa[l].z); da[3]=f2tf32(pa[l].w);                         \
            uint32_t* db = &sm[BBUF(buf) + r*STR + ldc*4];                        \
            db[0]=f2tf32(pb[l].x); db[1]=f2tf32(pb[l].y);                         \
            db[2]=f2tf32(pb[l].z); db[3]=f2tf32(pb[l].w);                         \
        }                                                                         \
    } while(0)

    float4 acc[4][4];
    #pragma unroll
    for (int i=0;i<4;i++)
        #pragma unroll
        for (int j=0;j<4;j++) acc[i][j] = make_float4(0.f,0.f,0.f,0.f);

    int nCh = K >> 5;
    GLOAD(0); SSTORE(0);
    __syncthreads();

    for (int i = 0; i < nCh; i++){
        int b = i & 1;
        if (i + 1 < nCh) GLOAD(i + 1);
        const uint32_t* sA = &sm[ABUF(b)];
        const uint32_t* sB = &sm[BBUF(b)];
        #pragma unroll
        for (int ks = 0; ks < 4; ks++){
            int k0 = ks*8;
            uint32_t af[4][4], bf[4][2];
            #pragma unroll
            for (int mt=0; mt<4; mt++){
                int ar = wr*64 + mt*16 + g;
                af[mt][0] = sA[ar*STR + k0 + t];
                af[mt][1] = sA[(ar+8)*STR + k0 + t];
                af[mt][2] = sA[ar*STR + k0 + t + 4];
                af[mt][3] = sA[(ar+8)*STR + k0 + t + 4];
            }
            #pragma unroll
            for (int nt=0; nt<4; nt++){
                int bn = wc*32 + nt*8 + g;
                bf[nt][0] = sB[bn*STR + k0 + t];
                bf[nt][1] = sB[bn*STR + k0 + t + 4];
            }
            #pragma unroll
            for (int mt=0; mt<4; mt++)
                #pragma unroll
                for (int nt=0; nt<4; nt++)
                    mma_tf32(acc[mt][nt], af[mt][0],af[mt][1],af[mt][2],af[mt][3],
                             bf[nt][0], bf[nt][1]);
        }
        if (i + 1 < nCh){
            __syncthreads();
            SSTORE(b ^ 1);
            __syncthreads();
        }
    }

    // ---- epilogue ----
    const float* biasb = bias ? bias + (long)z*biasBatch : (const float*)0;
    const float* caddb = Cadd ? Cadd + (long)z*caddBatch : (const float*)0;
    float* Cb = C + (long)z*cBatch;
    #pragma unroll
    for (int mt=0; mt<4; mt++){
        long row0 = brow + wr*64 + mt*16 + g;
        #pragma unroll
        for (int nt=0; nt<4; nt++){
            long col = bcol + wc*32 + nt*8 + 2*t;
            float2 v0 = make_float2(acc[mt][nt].x, acc[mt][nt].y);
            float2 v1 = make_float2(acc[mt][nt].z, acc[mt][nt].w);
            if (biasb){
                v0.x += biasb[col];   v0.y += biasb[col+1];
                v1.x += biasb[col];   v1.y += biasb[col+1];
            }
            if (caddb){
                float2 a0 = *reinterpret_cast<const float2*>(&caddb[row0*caddRow + col]);
                float2 a1 = *reinterpret_cast<const float2*>(&caddb[(row0+8)*caddRow + col]);
                v0.x += a0.x; v0.y += a0.y;
                v1.x += a1.x; v1.y += a1.y;
            }
            *reinterpret_cast<float2*>(&Cb[row0*cRow + col])     = v0;
            *reinterpret_cast<float2*>(&Cb[(row0+8)*cRow + col]) = v1;
        }
    }
    #undef GLOAD
    #undef SSTORE
}

// ---------------- gates + state update per recurrence step -------------------
__global__ void gates_step(int s){
    long i = (long)blockIdx.x*blockDim.x + threadIdx.x;
    if (i >= (long)NCMB*NT*DM) return;
    int cmb = (int)(i/((long)NT*DM));
    long nd = i%((long)NT*DM);
    int n = (int)(nd/DM), d = (int)(nd%DM);
    const float* g = s_g + (long)cmb*NT*GD + (long)n*GD;
    float ig = sigf(g[d]);
    float fg = sigf(g[DM+d]);
    float ug = tanhf(g[2*DM+d]);
    float og = sigf(g[3*DM+d]);
    float cp = s_c[i];
    float cn = fg*cp + ig*ug;
    float hn = og*tanhf(cn);
    if (cmb == 1){
        int kk = 15 - s;
        bool m = kk < s_len[n];
        if (m){ s_c[i]=cn; s_h[i]=hn; }
        s_ycat0[((long)n*KC+kk)*(2*DM) + DM + d] = m ? hn : 0.f;
    } else {
        s_c[i]=cn; s_h[i]=hn;
        if (cmb==0) s_ycat0[((long)n*KC+s)*(2*DM) + d] = hn;
        else if (s == s_len[n]-1)
            s_ylcat[((long)(cmb-2)*NT+n)*(2*DM) + d] = hn;
    }
}

__global__ void gates_last(const float* __restrict__ c0){
    long i = (long)blockIdx.x*blockDim.x + threadIdx.x;
    if (i >= 3L*NT*DM) return;
    int jb = (int)(i/((long)NT*DM));
    long nd = i%((long)NT*DM);
    int n = (int)(nd/DM), d = (int)(nd%DM);
    const float* g = s_gB + (long)jb*NT*GD + (long)n*GD;
    float ig=sigf(g[d]), fg=sigf(g[DM+d]), ug=tanhf(g[2*DM+d]), og=sigf(g[3*DM+d]);
    float cp = c0[(jb+1)*DM+d];
    float cn = fg*cp + ig*ug;
    float hn = og*tanhf(cn);
    s_ylcat[((long)jb*NT+n)*(2*DM) + DM + d] = hn;
}

__global__ void final_k(float* __restrict__ out){
    int n = blockIdx.x, d = threadIdx.x;
    float wf = s_Wx[(long)n*GD + d];
    float wi = s_Wx[(long)n*GD + DM + d];
    float wu = s_Wx[(long)n*GD + 2*DM + d];
    float wo = s_Wx[(long)n*GD + 3*DM + d];
    int len = s_len[n];
    float bf = 0.f;
    for (int k=0;k<len;k++){
        float y  = s_ys0 [((long)n*KC+k)*DM + d];
        float cc = s_cseq[((long)n*KC+k)*DM + d];
        bf += sigf(wf + y) * cc;
    }
    float bi = sigf (s_ysl[0L*NT*DM + (long)n*DM + d] + wi);
    float bu = tanhf(s_ysl[1L*NT*DM + (long)n*DM + d] + wu);
    float bo = sigf (s_ysl[2L*NT*DM + (long)n*DM + d] + wo);
    float ncv = bi*bu + bf;
    float nhv = bo*tanhf(ncv);
    out[(long)n*DM + d] = nhv;
    out[(long)NT*DM + (long)n*DM + d] = ncv;
}

// =============================================================================
extern "C" void kernel_launch(void* const* d_in, const int* in_sizes, int n_in,
                              void* d_out, int out_size) {
    const float* x        = (const float*)d_in[0];
    const float* h_tensor = (const float*)d_in[1];
    const float* c_tensor = (const float*)d_in[2];
    const int*   indice   = (const int*)  d_in[3];
    const float* W_w      = (const float*)d_in[4];
    const float* W_b      = (const float*)d_in[5];
    const float* h0       = (const float*)d_in[6];
    const float* c0       = (const float*)d_in[7];
    const float* Wih      = (const float*)d_in[8];
    const float* Whh      = (const float*)d_in[9];
    const float* bih      = (const float*)d_in[10];
    const float* bhh      = (const float*)d_in[11];
    const float* fc       = (const float*)d_in[12];
    float* out = (float*)d_out;

    float *p_xseq,*p_Wih5,*p_Whh5,*p_b5,*p_Gx,*p_h,*p_g,*p_Wx,
          *p_xlast,*p_WihB,*p_hb,*p_gB,*p_ycat0,*p_ys0,*p_ylcat,*p_ysl;
    cudaGetSymbolAddress((void**)&p_xseq,  s_xseq);
    cudaGetSymbolAddress((void**)&p_Wih5,  s_Wih5);
    cudaGetSymbolAddress((void**)&p_Whh5,  s_Whh5);
    cudaGetSymbolAddress((void**)&p_b5,    s_b5);
    cudaGetSymbolAddress((void**)&p_Gx,    s_Gx);
    cudaGetSymbolAddress((void**)&p_h,     s_h);
    cudaGetSymbolAddress((void**)&p_g,     s_g);
    cudaGetSymbolAddress((void**)&p_Wx,    s_Wx);
    cudaGetSymbolAddress((void**)&p_xlast, s_xlast);
    cudaGetSymbolAddress((void**)&p_WihB,  s_WihB);
    cudaGetSymbolAddress((void**)&p_hb,    s_hb);
    cudaGetSymbolAddress((void**)&p_gB,    s_gB);
    cudaGetSymbolAddress((void**)&p_ycat0, s_ycat0);
    cudaGetSymbolAddress((void**)&p_ys0,   s_ys0);
    cudaGetSymbolAddress((void**)&p_ylcat, s_ylcat);
    cudaGetSymbolAddress((void**)&p_ysl,   s_ysl);
    (void)in_sizes; (void)n_in; (void)out_size;

    const int SMEM_SZ = 4*128*STR*4;      // 73728 bytes
    cudaFuncSetAttribute(gemm_mma, cudaFuncAttributeMaxDynamicSharedMemorySize, SMEM_SZ);

    // 1) pack weights / gather / meta
    prep_weights<<<1024,256>>>(Wih,Whh,bih,bhh);
    gather_k<<<(int)(((long)NT*KC*(DM/4))/256),256>>>(h_tensor,c_tensor,indice);
    meta_k<<<512,256>>>(indice,h0,c0);

    // 2) Wx = x @ W_w^T + W_b        [4096,1024]
    gemm_mma<<<dim3(GD/128, NT/128, 1),256,SMEM_SZ>>>(
        x,0, W_w,0, W_b,0, (const float*)0,0,0,
        p_Wx,0,GD, NT,GD,DM, -1,0);

    // 3) Gx = xseq @ Wih5^T + b5, time-reversed rows for combo 1 (z==1)
    gemm_mma<<<dim3(GD/128, (NT*KC)/128, NCMB),256,SMEM_SZ>>>(
        p_xseq,0, p_Wih5,(long)GD*DM, p_b5,(long)GD, (const float*)0,0,0,
        p_Gx,(long)NT*KC*GD,GD, NT*KC,GD,DM, 1,15);

    // 4) one-step backward prep
    hb_k<<<12,256>>>(h0,Whh,bih,bhh);
    xlast_k<<<(int)(((long)NT*(DM/4)+255)/256),256>>>();

    // 5) the 16 recurrence steps (5 combos batched per step)
    long gatesN = (long)NCMB*NT*DM;
    for (int s = 0; s < KC; s++){
        gemm_mma<<<dim3(GD/128, NT/128, NCMB),256,SMEM_SZ>>>(
            p_h,(long)NT*DM, p_Whh5,(long)GD*DM, (const float*)0,0,
            p_Gx + (long)s*GD, (long)NT*KC*GD, KC*GD,
            p_g,(long)NT*GD,GD, NT,GD,DM, -1,0);
        gates_step<<<(int)((gatesN+255)/256),256>>>(s);
    }

    // 6) backward one-step for j=1..3
    gemm_mma<<<dim3(GD/128, NT/128, 3),256,SMEM_SZ>>>(
        p_xlast,0, p_WihB,(long)GD*DM, p_hb,(long)GD, (const float*)0,0,0,
        p_gB,(long)NT*GD,GD, NT,GD,DM, -1,0);
    gates_last<<<(int)((3L*NT*DM+255)/256),256>>>(c0);

    // 7) fc projections
    gemm_mma<<<dim3(DM/128, (NT*KC)/128, 1),256,SMEM_SZ>>>(
        p_ycat0,0, fc,0, (const float*)0,0, (const float*)0,0,0,
        p_ys0,0,DM, NT*KC,DM,2*DM, -1,0);
    gemm_mma<<<dim3(DM/128, NT/128, 3),256,SMEM_SZ>>>(
        p_ylcat,(long)NT*2*DM, fc + (long)DM*2*DM,(long)DM*2*DM,
        (const float*)0,0, (const float*)0,0,0,
        p_ysl,(long)NT*DM,DM, NT,DM,2*DM, -1,0);

    // 8) final combine -> (new_h, new_c)
    final_k<<<NT,DM>>>(out);
}